// round 14
// baseline (speedup 1.0000x reference)
#include <cuda_runtime.h>
#include <cuda_fp16.h>
#include <cstdint>

#define NND 50000
#define EDG 800000
#define NTILES 391
#define SAPAD 136          // padded k-stride in fp16 (272B = 17x16B, 4-bank shift/row)
#define NSCB 196           // ceil(50000/256) scan blocks

// ---------------- scratch ----------------------------------------------------
__device__ float g_u[NND * 128];               // masked PReLU(x), fp32
__device__ __align__(16) __half g_uh[NND * 128];  // fp16 gather plane of u
__device__ float g_U1[NND * 128];              // u + sum of u[src] over in-edges
__device__ float g_S[NND * 9];                 // sum of edge_attr over in-edges
__device__ float g_z[NND * 256];               // pre-BN hidden
__device__ float g_P[9 * 256];                 // W_e @ W1_bot
__device__ float g_q1[256];                    // b_e @ W1_bot
__device__ float g_cs[256];                    // column sums of z
__device__ float g_cq[256];                    // column sums of z^2
__device__ float g_a[256];                     // BN scale
__device__ float g_bb[256];                    // BN shift
__device__ __align__(16) __half g_Bz[256 * SAPAD];       // Wfold^T fp16 plane
__device__ __align__(16) __half g_Bo[2 * 128 * SAPAD];   // W2^T [kc] fp16 planes
// CSR scratch
__device__ int g_cnt[NND];
__device__ int g_offp[NND];
__device__ int g_bs[NSCB];
__device__ int g_bo[NSCB + 1];
__device__ int g_off[NND + 1];
__device__ int g_cur[NND];
__device__ int2 g_se[EDG];                     // (src, edge_id)

// ---------------- helpers -----------------------------------------------------
__device__ __forceinline__ uint32_t smem_u32(const void* p) {
    uint32_t a;
    asm("{ .reg .u64 t; cvta.to.shared.u64 t, %1; cvt.u32.u64 %0, t; }" : "=r"(a) : "l"(p));
    return a;
}
__device__ __forceinline__ void ldsm4(uint32_t& r0, uint32_t& r1, uint32_t& r2, uint32_t& r3,
                                      uint32_t addr) {
    asm volatile("ldmatrix.sync.aligned.m8n8.x4.shared.b16 {%0,%1,%2,%3}, [%4];"
                 : "=r"(r0), "=r"(r1), "=r"(r2), "=r"(r3) : "r"(addr));
}
__device__ __forceinline__ void mma_f16(float* c, const uint32_t* a, uint32_t b0, uint32_t b1) {
    asm volatile(
        "mma.sync.aligned.m16n8k16.row.col.f32.f16.f16.f32 "
        "{%0,%1,%2,%3}, {%4,%5,%6,%7}, {%8,%9}, {%0,%1,%2,%3};"
        : "+f"(c[0]), "+f"(c[1]), "+f"(c[2]), "+f"(c[3])
        : "r"(a[0]), "r"(a[1]), "r"(a[2]), "r"(a[3]), "r"(b0), "r"(b1));
}
__device__ __forceinline__ uint32_t pack_f16(float a, float b) {
    __half2 h = make_half2(__float2half_rn(a), __float2half_rn(b));
    return *(uint32_t*)&h;
}
// fp32x4 -> fp16 hi/lo split, store at element index idx (mult of 4)
__device__ __forceinline__ void split_store_h(__half* hi, __half* lo, int idx, float4 g) {
    __half hx = __float2half_rn(g.x), hy = __float2half_rn(g.y);
    __half hz = __float2half_rn(g.z), hw = __float2half_rn(g.w);
    __half lx = __float2half_rn(g.x - __half2float(hx));
    __half ly = __float2half_rn(g.y - __half2float(hy));
    __half lz = __float2half_rn(g.z - __half2float(hz));
    __half lw = __float2half_rn(g.w - __half2float(hw));
    __half2 h0 = make_half2(hx, hy), h1 = make_half2(hz, hw);
    __half2 l0 = make_half2(lx, ly), l1 = make_half2(lz, lw);
    uint2 h, l;
    h.x = *(uint32_t*)&h0; h.y = *(uint32_t*)&h1;
    l.x = *(uint32_t*)&l0; l.y = *(uint32_t*)&l1;
    *(uint2*)&hi[idx] = h;
    *(uint2*)&lo[idx] = l;
}

// ---------------- kernel 1: u = PReLU(x) (fp32 + fp16 planes) ----------------
__global__ void __launch_bounds__(256) prep_kernel(const float* __restrict__ x,
                                                   const float* __restrict__ pa) {
    const float a = *pa;
    size_t i = (size_t)blockIdx.x * 256 + threadIdx.x;
    if (i >= (size_t)NND * 32) return;
    float4 g = *(const float4*)&x[i * 4];
    g.x = g.x >= 0.f ? g.x : a * g.x;
    g.y = g.y >= 0.f ? g.y : a * g.y;
    g.z = g.z >= 0.f ? g.z : a * g.z;
    g.w = g.w >= 0.f ? g.w : a * g.w;
    *(float4*)&g_u[i * 4] = g;
    uint2 h;
    h.x = pack_f16(g.x, g.y);
    h.y = pack_f16(g.z, g.w);
    *(uint2*)&g_uh[i * 4] = h;
}

// ---------------- kernel 2: zero masked rows ---------------------------------
__global__ void mask_kernel(const int* __restrict__ idx, int n) {
    int i = blockIdx.x;
    if (i >= n) return;
    unsigned v = (unsigned)idx[i];
    if (v < NND) {
        *(float4*)&g_u[(size_t)v * 128 + threadIdx.x * 4] =
            make_float4(0.f, 0.f, 0.f, 0.f);
        *(uint2*)&g_uh[(size_t)v * 128 + threadIdx.x * 4] = make_uint2(0u, 0u);
    }
}

// ---------------- CSR build ---------------------------------------------------
__global__ void __launch_bounds__(256) hist_kernel(const int* __restrict__ ei) {
    int e = blockIdx.x * 256 + threadIdx.x;
    if (e >= EDG) return;
    unsigned s = (unsigned)ei[e];
    unsigned d = (unsigned)ei[EDG + e];
    if (s >= NND || d >= NND) return;
    atomicAdd(&g_cnt[d], 1);
}

__global__ void __launch_bounds__(256) scan1_kernel() {
    __shared__ int s[256];
    int t = threadIdx.x;
    int idx = blockIdx.x * 256 + t;
    int v = (idx < NND) ? g_cnt[idx] : 0;
    int val = v;
    s[t] = val;
    __syncthreads();
#pragma unroll
    for (int off = 1; off < 256; off <<= 1) {
        int add = (t >= off) ? s[t - off] : 0;
        __syncthreads();
        val += add;
        s[t] = val;
        __syncthreads();
    }
    if (idx < NND) g_offp[idx] = val - v;
    if (t == 255) g_bs[blockIdx.x] = val;
}

__global__ void __launch_bounds__(256) scan2_kernel() {
    __shared__ int s[256];
    int t = threadIdx.x;
    int v = (t < NSCB) ? g_bs[t] : 0;
    int val = v;
    s[t] = val;
    __syncthreads();
#pragma unroll
    for (int off = 1; off < 256; off <<= 1) {
        int add = (t >= off) ? s[t - off] : 0;
        __syncthreads();
        val += add;
        s[t] = val;
        __syncthreads();
    }
    if (t < NSCB) g_bo[t] = val - v;
    if (t == 255) g_bo[NSCB] = val;
}

__global__ void __launch_bounds__(256) scan3_kernel() {
    int idx = blockIdx.x * 256 + threadIdx.x;
    if (idx < NND) {
        int o = g_offp[idx] + g_bo[blockIdx.x];
        g_off[idx] = o;
        g_cur[idx] = o;
    }
    if (idx == 0) g_off[NND] = g_bo[NSCB];
}

__global__ void __launch_bounds__(256) fill_kernel(const int* __restrict__ ei) {
    int e = blockIdx.x * 256 + threadIdx.x;
    if (e >= EDG) return;
    unsigned s = (unsigned)ei[e];
    unsigned d = (unsigned)ei[EDG + e];
    if (s >= NND || d >= NND) return;
    int p = atomicAdd(&g_cur[d], 1);
    g_se[p] = make_int2((int)s, e);
}

// ---------------- aggregate: U1[v] = u[v] + sum uh[src]; S[v] = sum ea -------
__device__ __forceinline__ void add_h4(float4& acc, uint2 v) {
    float2 f0 = __half22float2(*(__half2*)&v.x);
    float2 f1 = __half22float2(*(__half2*)&v.y);
    acc.x += f0.x; acc.y += f0.y; acc.z += f1.x; acc.w += f1.y;
}
__global__ void __launch_bounds__(256) aggregate_kernel(const float* __restrict__ ea) {
    int w = (int)((blockIdx.x * 256u + threadIdx.x) >> 5);
    int lane = threadIdx.x & 31;
    if (w >= NND) return;
    int nb = g_off[w], ne = g_off[w + 1];
    float4 acc = *(const float4*)&g_u[(size_t)w * 128 + lane * 4];
    float sa = 0.f;
    int i = nb;
    for (; i + 4 <= ne; i += 4) {
        int2 p0 = g_se[i], p1 = g_se[i + 1], p2 = g_se[i + 2], p3 = g_se[i + 3];
        uint2 a = *(const uint2*)&g_uh[(size_t)p0.x * 128 + lane * 4];
        uint2 b = *(const uint2*)&g_uh[(size_t)p1.x * 128 + lane * 4];
        uint2 c = *(const uint2*)&g_uh[(size_t)p2.x * 128 + lane * 4];
        uint2 d = *(const uint2*)&g_uh[(size_t)p3.x * 128 + lane * 4];
        add_h4(acc, a); add_h4(acc, b); add_h4(acc, c); add_h4(acc, d);
        if (lane < 9) {
            sa += ea[(size_t)p0.y * 9 + lane] + ea[(size_t)p1.y * 9 + lane]
                + ea[(size_t)p2.y * 9 + lane] + ea[(size_t)p3.y * 9 + lane];
        }
    }
    for (; i < ne; i++) {
        int2 p0 = g_se[i];
        uint2 a = *(const uint2*)&g_uh[(size_t)p0.x * 128 + lane * 4];
        add_h4(acc, a);
        if (lane < 9) sa += ea[(size_t)p0.y * 9 + lane];
    }
    *(float4*)&g_U1[(size_t)w * 128 + lane * 4] = acc;
    if (lane < 9) g_S[(size_t)w * 9 + lane] = sa;
}

// ---------------- merged weight prep: 0-7 fold_bz, 8-15 fold_bo, 16-25 precomp
__global__ void __launch_bounds__(256) weights_kernel(const float* __restrict__ Wenc,
                                                      const float* __restrict__ W1,
                                                      const float* __restrict__ W2,
                                                      const float* __restrict__ We,
                                                      const float* __restrict__ be) {
    __shared__ float ws[32 * 128];
    const int b = blockIdx.x;
    if (b < 8) {
        const int k0 = b * 16, c = threadIdx.x;
        for (int i = threadIdx.x; i < 512; i += 256)
            ((float4*)ws)[i] = ((const float4*)(Wenc + k0 * 128))[i];
        __syncthreads();
        float acc[16];
#pragma unroll
        for (int r = 0; r < 16; r++) acc[r] = 0.f;
        for (int m = 0; m < 128; m++) {
            float w1 = W1[m * 256 + c];
#pragma unroll
            for (int r = 0; r < 16; r++) acc[r] += ws[r * 128 + m] * w1;
        }
        uint32_t h[8];
#pragma unroll
        for (int r = 0; r < 8; r++) h[r] = pack_f16(acc[2 * r], acc[2 * r + 1]);
        uint4* ph = (uint4*)&g_Bz[c * SAPAD + k0];
        ph[0] = make_uint4(h[0], h[1], h[2], h[3]);
        ph[1] = make_uint4(h[4], h[5], h[6], h[7]);
    } else if (b < 16) {
        const int k0 = (b - 8) * 32;
        const int kc = k0 >> 7, kk0 = k0 & 127;
        for (int i = threadIdx.x; i < 1024; i += 256)
            ((float4*)ws)[i] = ((const float4*)(W2 + k0 * 128))[i];
        __syncthreads();
        const int n = threadIdx.x >> 1, kl0 = (threadIdx.x & 1) * 16;
        uint32_t h[8];
#pragma unroll
        for (int q = 0; q < 8; q++)
            h[q] = pack_f16(ws[(kl0 + 2 * q) * 128 + n], ws[(kl0 + 2 * q + 1) * 128 + n]);
        uint4* ph = (uint4*)&g_Bo[kc * 128 * SAPAD + n * SAPAD + kk0 + kl0];
        ph[0] = make_uint4(h[0], h[1], h[2], h[3]);
        ph[1] = make_uint4(h[4], h[5], h[6], h[7]);
    } else {
        const int j = b - 16, c = threadIdx.x;
        if (c < 128) ws[c] = (j < 9) ? We[j * 128 + c] : be[c];
        __syncthreads();
        float acc = 0.f;
#pragma unroll 8
        for (int m = 0; m < 128; m++) acc += ws[m] * W1[(128 + m) * 256 + c];
        if (j < 9) g_P[j * 256 + c] = acc;
        else       g_q1[c] = acc;
    }
}

// ---------------- kernel 5: HMMA gemm_z (fp16 2-term) ------------------------
#define ZA_HI 0
#define ZA_LO 34816
#define ZB    69632
#define ZP    139264
#define ZQ1   148480
#define ZPC   149504
#define ZSS   150528
#define ZCS   156672
#define ZCQ   157696
#define ZSMEM 158720

__global__ void __launch_bounds__(256, 1) gemm_z_tc(const float* __restrict__ b1) {
    extern __shared__ __align__(16) unsigned char sm[];
    const uint32_t sbase = smem_u32(sm);
    const int tid = threadIdx.x, w = tid >> 5, lid = tid & 31;
    const int rowBase = blockIdx.x * 128;
    float* Psm = (float*)(sm + ZP);
    float* Q1s = (float*)(sm + ZQ1);
    float* PCs = (float*)(sm + ZPC);
    float* Ssm = (float*)(sm + ZSS);
    float* CSs = (float*)(sm + ZCS);
    float* CQs = (float*)(sm + ZCQ);

    for (int i = tid; i < 2304; i += 256) Psm[i] = g_P[i];
    Q1s[tid] = g_q1[tid];
    PCs[tid] = g_P[7 * 256 + tid] + b1[tid];
    CSs[tid] = 0.f;
    CQs[tid] = 0.f;
    for (int i = tid; i < 1280; i += 256) {
        int r = i / 10, j = i % 10;
        int grow = rowBase + r;
        float v = 0.f;
        if (grow < NND)
            v = (j < 9) ? g_S[(size_t)grow * 9 + j]
                        : (float)(g_off[grow + 1] - g_off[grow]);
        Ssm[r * 12 + j] = v;
    }
    // stage A hi/lo (fp16)
    {
        int r = tid >> 1, ch = (tid & 1) * 64;
        int grow = rowBase + r;
        __half* ah = (__half*)(sm + ZA_HI);
        __half* al = (__half*)(sm + ZA_LO);
        if (grow < NND) {
            const float* src = &g_U1[(size_t)grow * 128 + ch];
#pragma unroll
            for (int j = 0; j < 16; j++)
                split_store_h(ah, al, r * SAPAD + ch + j * 4, *(const float4*)&src[j * 4]);
        } else {
            float4 zz = make_float4(0.f, 0.f, 0.f, 0.f);
#pragma unroll
            for (int j = 0; j < 16; j++) split_store_h(ah, al, r * SAPAD + ch + j * 4, zz);
        }
    }
    for (int i = tid * 16; i < 69632; i += 256 * 16)
        *(float4*)(sm + ZB + i) = *(const float4*)((const unsigned char*)g_Bz + i);
    __syncthreads();

    float acc[8][4][4];
#pragma unroll
    for (int m = 0; m < 8; m++)
#pragma unroll
        for (int n = 0; n < 4; n++)
#pragma unroll
            for (int e = 0; e < 4; e++) acc[m][n][e] = 0.f;

    const uint32_t a_lane = (uint32_t)((((lid & 7) + 8 * ((lid >> 3) & 1)) * SAPAD + 8 * (lid >> 4)) * 2);
    const uint32_t b_lane = (uint32_t)((((lid & 7) + 8 * (lid >> 4)) * SAPAD + 8 * ((lid >> 3) & 1)) * 2);
    const uint32_t bb = sbase + ZB + b_lane + (uint32_t)(w * 32 * SAPAD) * 2;

#pragma unroll
    for (int t = 0; t < 2; t++) {
        uint32_t abase = sbase + (t == 1 ? ZA_LO : ZA_HI) + a_lane;
#pragma unroll
        for (int kt = 0; kt < 8; kt++) {
            uint32_t k2 = kt * 32;
            uint32_t af[8][4];
#pragma unroll
            for (int mt = 0; mt < 8; mt++)
                ldsm4(af[mt][0], af[mt][1], af[mt][2], af[mt][3],
                      abase + mt * (16 * SAPAD * 2) + k2);
            uint32_t bf0[4], bf1[4];
            ldsm4(bf0[0], bf0[1], bf0[2], bf0[3], bb + k2);
            ldsm4(bf1[0], bf1[1], bf1[2], bf1[3], bb + 16 * SAPAD * 2 + k2);
#pragma unroll
            for (int mt = 0; mt < 8; mt++) {
                mma_f16(acc[mt][0], af[mt], bf0[0], bf0[1]);
                mma_f16(acc[mt][1], af[mt], bf0[2], bf0[3]);
                mma_f16(acc[mt][2], af[mt], bf1[0], bf1[1]);
                mma_f16(acc[mt][3], af[mt], bf1[2], bf1[3]);
            }
        }
    }

    // epilogue
    const int gid = lid >> 2, tig = lid & 3;
    float colS[8], colQ[8];
#pragma unroll
    for (int e = 0; e < 8; e++) { colS[e] = 0.f; colQ[e] = 0.f; }
#pragma unroll
    for (int mt = 0; mt < 8; mt++) {
        int r0 = mt * 16 + gid, r1 = r0 + 8;
        int gr0 = rowBase + r0, gr1 = rowBase + r1;
        bool v0 = gr0 < NND, v1 = gr1 < NND;
        float s0[10], s1[10];
#pragma unroll
        for (int j = 0; j < 10; j++) { s0[j] = Ssm[r0 * 12 + j]; s1[j] = Ssm[r1 * 12 + j]; }
        float d0 = s0[9] + 1.f, d1v = s1[9] + 1.f;
#pragma unroll
        for (int nt = 0; nt < 4; nt++) {
            int c0 = w * 32 + nt * 8 + 2 * tig, c1 = c0 + 1;
            float v00 = acc[mt][nt][0] + d0 * Q1s[c0] + PCs[c0];
            float v01 = acc[mt][nt][1] + d0 * Q1s[c1] + PCs[c1];
            float v10 = acc[mt][nt][2] + d1v * Q1s[c0] + PCs[c0];
            float v11 = acc[mt][nt][3] + d1v * Q1s[c1] + PCs[c1];
#pragma unroll
            for (int j = 0; j < 9; j++) {
                float p0 = Psm[j * 256 + c0], p1 = Psm[j * 256 + c1];
                v00 += s0[j] * p0; v01 += s0[j] * p1;
                v10 += s1[j] * p0; v11 += s1[j] * p1;
            }
            if (v0) {
                *(float2*)&g_z[(size_t)gr0 * 256 + c0] = make_float2(v00, v01);
                colS[nt * 2] += v00; colQ[nt * 2] += v00 * v00;
                colS[nt * 2 + 1] += v01; colQ[nt * 2 + 1] += v01 * v01;
            }
            if (v1) {
                *(float2*)&g_z[(size_t)gr1 * 256 + c0] = make_float2(v10, v11);
                colS[nt * 2] += v10; colQ[nt * 2] += v10 * v10;
                colS[nt * 2 + 1] += v11; colQ[nt * 2 + 1] += v11 * v11;
            }
        }
    }
#pragma unroll
    for (int nt = 0; nt < 4; nt++) {
#pragma unroll
        for (int e = 0; e < 2; e++) {
            int c = w * 32 + nt * 8 + 2 * tig + e;
            atomicAdd(&CSs[c], colS[nt * 2 + e]);
            atomicAdd(&CQs[c], colQ[nt * 2 + e]);
        }
    }
    __syncthreads();
    atomicAdd(&g_cs[tid], CSs[tid]);
    atomicAdd(&g_cq[tid], CQs[tid]);
}

// ---------------- kernel 6: BN finalize --------------------------------------
__global__ void bn_kernel(const float* __restrict__ gamma,
                          const float* __restrict__ beta) {
    int c = threadIdx.x;
    const float invN = 1.f / (float)NND;
    float m = g_cs[c] * invN;
    float var = g_cq[c] * invN - m * m;
    float av = gamma[c] * rsqrtf(var + 1e-5f);
    g_a[c] = av;
    g_bb[c] = beta[c] - m * av;
}

// ---------------- kernel 7: HMMA gemm_o (fp16 2-term) ------------------------
#define OA_HI 0
#define OA_LO 34816
#define OB    69632
#define OSA   139264
#define OSB   140288
#define OB2   141312
#define OSMEM 141824

__global__ void __launch_bounds__(256, 1) gemm_o_tc(const float* __restrict__ b2,
                                                    float* __restrict__ out) {
    extern __shared__ __align__(16) unsigned char sm[];
    const uint32_t sbase = smem_u32(sm);
    const int tid = threadIdx.x, w = tid >> 5, lid = tid & 31;
    const int rowBase = blockIdx.x * 128;
    float* SAs = (float*)(sm + OSA);
    float* SBs = (float*)(sm + OSB);
    float* B2s = (float*)(sm + OB2);
    SAs[tid] = g_a[tid];
    SBs[tid] = g_bb[tid];
    if (tid < 128) B2s[tid] = b2[tid];
    for (int i = tid * 16; i < 69632; i += 256 * 16)
        *(float4*)(sm + OB + i) = *(const float4*)((const unsigned char*)g_Bo + i);

    float acc[4][4][4];
#pragma unroll
    for (int m = 0; m < 4; m++)
#pragma unroll
        for (int n = 0; n < 4; n++)
#pragma unroll
            for (int e = 0; e < 4; e++) acc[m][n][e] = 0.f;

    const uint32_t a_lane = (uint32_t)((((lid & 7) + 8 * ((lid >> 3) & 1)) * SAPAD + 8 * (lid >> 4)) * 2);
    const uint32_t b_lane = (uint32_t)((((lid & 7) + 8 * (lid >> 4)) * SAPAD + 8 * ((lid >> 3) & 1)) * 2);
    const uint32_t a_mbase = (uint32_t)((w >> 2) * 64 * SAPAD * 2);
    const uint32_t b_nbase = (uint32_t)((w & 3) * 32 * SAPAD * 2);

    for (int kc = 0; kc < 2; kc++) {
        __syncthreads();
        {
            int r = tid >> 1, ch = (tid & 1) * 64;
            int grow = rowBase + r;
            __half* ah = (__half*)(sm + OA_HI);
            __half* al = (__half*)(sm + OA_LO);
            if (grow < NND) {
                const float* src = &g_z[(size_t)grow * 256 + kc * 128 + ch];
#pragma unroll
                for (int j = 0; j < 16; j++) {
                    float4 g = *(const float4*)&src[j * 4];
                    int c0 = kc * 128 + ch + j * 4;
                    g.x = fmaxf(g.x * SAs[c0 + 0] + SBs[c0 + 0], 0.f);
                    g.y = fmaxf(g.y * SAs[c0 + 1] + SBs[c0 + 1], 0.f);
                    g.z = fmaxf(g.z * SAs[c0 + 2] + SBs[c0 + 2], 0.f);
                    g.w = fmaxf(g.w * SAs[c0 + 3] + SBs[c0 + 3], 0.f);
                    split_store_h(ah, al, r * SAPAD + ch + j * 4, g);
                }
            } else {
                float4 zz = make_float4(0.f, 0.f, 0.f, 0.f);
#pragma unroll
                for (int j = 0; j < 16; j++) split_store_h(ah, al, r * SAPAD + ch + j * 4, zz);
            }
        }
        __syncthreads();
        const uint32_t bb = sbase + OB + (uint32_t)(kc * 34816) + b_lane + b_nbase;
#pragma unroll
        for (int t = 0; t < 2; t++) {
            uint32_t abase = sbase + (t == 1 ? OA_LO : OA_HI) + a_lane + a_mbase;
#pragma unroll
            for (int kt = 0; kt < 8; kt++) {
                uint32_t k2 = kt * 32;
                uint32_t af[4][4];
#pragma unroll
                for (int mt = 0; mt < 4; mt++)
                    ldsm4(af[mt][0], af[mt][1], af[mt][2], af[mt][3],
                          abase + mt * (16 * SAPAD * 2) + k2);
                uint32_t bf0[4], bf1[4];
                ldsm4(bf0[0], bf0[1], bf0[2], bf0[3], bb + k2);
                ldsm4(bf1[0], bf1[1], bf1[2], bf1[3], bb + 16 * SAPAD * 2 + k2);
#pragma unroll
                for (int mt = 0; mt < 4; mt++) {
                    mma_f16(acc[mt][0], af[mt], bf0[0], bf0[1]);
                    mma_f16(acc[mt][1], af[mt], bf0[2], bf0[3]);
                    mma_f16(acc[mt][2], af[mt], bf1[0], bf1[1]);
                    mma_f16(acc[mt][3], af[mt], bf1[2], bf1[3]);
                }
            }
        }
    }

    const int gid = lid >> 2, tig = lid & 3;
#pragma unroll
    for (int mt = 0; mt < 4; mt++) {
        int r0 = (w >> 2) * 64 + mt * 16 + gid, r1 = r0 + 8;
        int gr0 = rowBase + r0, gr1 = rowBase + r1;
#pragma unroll
        for (int nt = 0; nt < 4; nt++) {
            int c0 = (w & 3) * 32 + nt * 8 + 2 * tig;
            if (gr0 < NND)
                *(float2*)&out[(size_t)gr0 * 128 + c0] =
                    make_float2(acc[mt][nt][0] + B2s[c0], acc[mt][nt][1] + B2s[c0 + 1]);
            if (gr1 < NND)
                *(float2*)&out[(size_t)gr1 * 128 + c0] =
                    make_float2(acc[mt][nt][2] + B2s[c0], acc[mt][nt][3] + B2s[c0 + 1]);
        }
    }
}

// ---------------- launch ----------------------------------------------------
extern "C" void kernel_launch(void* const* d_in, const int* in_sizes, int n_in,
                              void* d_out, int out_size) {
    const float* x     = (const float*)d_in[0];
    const int*   ei    = (const int*)d_in[1];
    const float* ea    = (const float*)d_in[2];
    const int*   mask  = (const int*)d_in[3];
    const float* pa    = (const float*)d_in[4];
    const float* Wenc  = (const float*)d_in[5];
    const float* We    = (const float*)d_in[6];
    const float* be    = (const float*)d_in[7];
    const float* W1    = (const float*)d_in[8];
    const float* b1    = (const float*)d_in[9];
    const float* gamma = (const float*)d_in[10];
    const float* beta  = (const float*)d_in[11];
    const float* W2    = (const float*)d_in[12];
    const float* b2    = (const float*)d_in[13];
    float*       out   = (float*)d_out;
    const int nmask = in_sizes[3];

    cudaFuncSetAttribute(gemm_z_tc, cudaFuncAttributeMaxDynamicSharedMemorySize, ZSMEM);
    cudaFuncSetAttribute(gemm_o_tc, cudaFuncAttributeMaxDynamicSharedMemorySize, OSMEM);

    void *pcnt, *pcs, *pcq;
    cudaGetSymbolAddress(&pcnt, g_cnt);
    cudaGetSymbolAddress(&pcs, g_cs);
    cudaGetSymbolAddress(&pcq, g_cq);
    cudaMemsetAsync(pcnt, 0, sizeof(int) * NND, 0);
    cudaMemsetAsync(pcs, 0, sizeof(float) * 256, 0);
    cudaMemsetAsync(pcq, 0, sizeof(float) * 256, 0);

    prep_kernel<<<(NND * 32 + 255) / 256, 256>>>(x, pa);
    if (nmask > 0) mask_kernel<<<nmask, 32>>>(mask, nmask);
    hist_kernel<<<(EDG + 255) / 256, 256>>>(ei);
    scan1_kernel<<<NSCB, 256>>>();
    scan2_kernel<<<1, 256>>>();
    scan3_kernel<<<NSCB, 256>>>();
    fill_kernel<<<(EDG + 255) / 256, 256>>>(ei);
    aggregate_kernel<<<(NND * 32 + 255) / 256, 256>>>(ea);
    weights_kernel<<<26, 256>>>(Wenc, W1, W2, We, be);
    gemm_z_tc<<<NTILES, 256, ZSMEM>>>(b1);
    bn_kernel<<<1, 256>>>(gamma, beta);
    gemm_o_tc<<<NTILES, 256, OSMEM>>>(b2, out);
}

// round 15
// speedup vs baseline: 1.1212x; 1.1212x over previous
#include <cuda_runtime.h>
#include <cuda_fp16.h>
#include <cstdint>

#define NND 50000
#define EDG 800000
#define NTILES 391
#define SAPAD 136          // padded k-stride in fp16 (272B = 17x16B, 4-bank shift/row)
#define NSCB 196           // ceil(50000/256) scan blocks

// ---------------- scratch ----------------------------------------------------
__device__ float g_u[NND * 128];               // masked PReLU(x)
__device__ float g_U1[NND * 128];              // u + sum of u[src] over in-edges
__device__ float g_S[NND * 9];                 // sum of edge_attr over in-edges
__device__ float g_z[NND * 256];               // pre-BN hidden
__device__ float g_P[9 * 256];                 // W_e @ W1_bot
__device__ float g_q1[256];                    // b_e @ W1_bot
__device__ float g_cs[256];                    // column sums of z
__device__ float g_cq[256];                    // column sums of z^2
__device__ float g_a[256];                     // BN scale
__device__ float g_bb[256];                    // BN shift
__device__ __align__(16) __half g_Bz[256 * SAPAD];       // Wfold^T fp16 plane
__device__ __align__(16) __half g_Bo[2 * 128 * SAPAD];   // W2^T [kc] fp16 planes
// CSR scratch
__device__ int g_cnt[NND];
__device__ int g_offp[NND];
__device__ int g_bs[NSCB];
__device__ int g_bo[NSCB + 1];
__device__ int g_off[NND + 1];
__device__ int g_cur[NND];
__device__ int2 g_se[EDG];                     // (src, edge_id)

// ---------------- helpers -----------------------------------------------------
__device__ __forceinline__ uint32_t smem_u32(const void* p) {
    uint32_t a;
    asm("{ .reg .u64 t; cvta.to.shared.u64 t, %1; cvt.u32.u64 %0, t; }" : "=r"(a) : "l"(p));
    return a;
}
__device__ __forceinline__ void ldsm4(uint32_t& r0, uint32_t& r1, uint32_t& r2, uint32_t& r3,
                                      uint32_t addr) {
    asm volatile("ldmatrix.sync.aligned.m8n8.x4.shared.b16 {%0,%1,%2,%3}, [%4];"
                 : "=r"(r0), "=r"(r1), "=r"(r2), "=r"(r3) : "r"(addr));
}
__device__ __forceinline__ void mma_f16(float* c, const uint32_t* a, uint32_t b0, uint32_t b1) {
    asm volatile(
        "mma.sync.aligned.m16n8k16.row.col.f32.f16.f16.f32 "
        "{%0,%1,%2,%3}, {%4,%5,%6,%7}, {%8,%9}, {%0,%1,%2,%3};"
        : "+f"(c[0]), "+f"(c[1]), "+f"(c[2]), "+f"(c[3])
        : "r"(a[0]), "r"(a[1]), "r"(a[2]), "r"(a[3]), "r"(b0), "r"(b1));
}
__device__ __forceinline__ uint32_t pack_f16(float a, float b) {
    __half2 h = make_half2(__float2half_rn(a), __float2half_rn(b));
    return *(uint32_t*)&h;
}
// fp32x4 -> fp16 (single plane), store at element index idx (mult of 4)
__device__ __forceinline__ void store_h4(__half* hi, int idx, float4 g) {
    uint2 h;
    h.x = pack_f16(g.x, g.y);
    h.y = pack_f16(g.z, g.w);
    *(uint2*)&hi[idx] = h;
}

// ---------------- kernel 1: u = PReLU(x) -------------------------------------
__global__ void __launch_bounds__(256) prep_kernel(const float* __restrict__ x,
                                                   const float* __restrict__ pa) {
    const float a = *pa;
    size_t i = (size_t)blockIdx.x * 256 + threadIdx.x;
    if (i >= (size_t)NND * 32) return;
    float4 g = *(const float4*)&x[i * 4];
    g.x = g.x >= 0.f ? g.x : a * g.x;
    g.y = g.y >= 0.f ? g.y : a * g.y;
    g.z = g.z >= 0.f ? g.z : a * g.z;
    g.w = g.w >= 0.f ? g.w : a * g.w;
    *(float4*)&g_u[i * 4] = g;
}

// ---------------- kernel 2: zero masked rows ---------------------------------
__global__ void mask_kernel(const int* __restrict__ idx, int n) {
    int i = blockIdx.x;
    if (i >= n) return;
    unsigned v = (unsigned)idx[i];
    if (v < NND)
        *(float4*)&g_u[(size_t)v * 128 + threadIdx.x * 4] =
            make_float4(0.f, 0.f, 0.f, 0.f);
}

// ---------------- CSR build ---------------------------------------------------
__global__ void __launch_bounds__(256) hist_kernel(const int* __restrict__ ei) {
    int e = blockIdx.x * 256 + threadIdx.x;
    if (e >= EDG) return;
    unsigned s = (unsigned)ei[e];
    unsigned d = (unsigned)ei[EDG + e];
    if (s >= NND || d >= NND) return;
    atomicAdd(&g_cnt[d], 1);
}

__global__ void __launch_bounds__(256) scan1_kernel() {
    __shared__ int s[256];
    int t = threadIdx.x;
    int idx = blockIdx.x * 256 + t;
    int v = (idx < NND) ? g_cnt[idx] : 0;
    int val = v;
    s[t] = val;
    __syncthreads();
#pragma unroll
    for (int off = 1; off < 256; off <<= 1) {
        int add = (t >= off) ? s[t - off] : 0;
        __syncthreads();
        val += add;
        s[t] = val;
        __syncthreads();
    }
    if (idx < NND) g_offp[idx] = val - v;
    if (t == 255) g_bs[blockIdx.x] = val;
}

__global__ void __launch_bounds__(256) scan2_kernel() {
    __shared__ int s[256];
    int t = threadIdx.x;
    int v = (t < NSCB) ? g_bs[t] : 0;
    int val = v;
    s[t] = val;
    __syncthreads();
#pragma unroll
    for (int off = 1; off < 256; off <<= 1) {
        int add = (t >= off) ? s[t - off] : 0;
        __syncthreads();
        val += add;
        s[t] = val;
        __syncthreads();
    }
    if (t < NSCB) g_bo[t] = val - v;
    if (t == 255) g_bo[NSCB] = val;
}

__global__ void __launch_bounds__(256) scan3_kernel() {
    int idx = blockIdx.x * 256 + threadIdx.x;
    if (idx < NND) {
        int o = g_offp[idx] + g_bo[blockIdx.x];
        g_off[idx] = o;
        g_cur[idx] = o;
    }
    if (idx == 0) g_off[NND] = g_bo[NSCB];
}

__global__ void __launch_bounds__(256) fill_kernel(const int* __restrict__ ei) {
    int e = blockIdx.x * 256 + threadIdx.x;
    if (e >= EDG) return;
    unsigned s = (unsigned)ei[e];
    unsigned d = (unsigned)ei[EDG + e];
    if (s >= NND || d >= NND) return;
    int p = atomicAdd(&g_cur[d], 1);
    g_se[p] = make_int2((int)s, e);
}

// ---------------- aggregate: U1[v] = u[v] + sum u[src]; S[v] = sum ea --------
__global__ void __launch_bounds__(256) aggregate_kernel(const float* __restrict__ ea) {
    int w = (int)((blockIdx.x * 256u + threadIdx.x) >> 5);
    int lane = threadIdx.x & 31;
    if (w >= NND) return;
    int nb = g_off[w], ne = g_off[w + 1];
    float4 acc = *(const float4*)&g_u[(size_t)w * 128 + lane * 4];
    float sa = 0.f;
    int i = nb;
    for (; i + 4 <= ne; i += 4) {
        int2 p0 = g_se[i], p1 = g_se[i + 1], p2 = g_se[i + 2], p3 = g_se[i + 3];
        float4 a = *(const float4*)&g_u[(size_t)p0.x * 128 + lane * 4];
        float4 b = *(const float4*)&g_u[(size_t)p1.x * 128 + lane * 4];
        float4 c = *(const float4*)&g_u[(size_t)p2.x * 128 + lane * 4];
        float4 d = *(const float4*)&g_u[(size_t)p3.x * 128 + lane * 4];
        acc.x += a.x + b.x + c.x + d.x;
        acc.y += a.y + b.y + c.y + d.y;
        acc.z += a.z + b.z + c.z + d.z;
        acc.w += a.w + b.w + c.w + d.w;
        if (lane < 9) {
            sa += ea[(size_t)p0.y * 9 + lane] + ea[(size_t)p1.y * 9 + lane]
                + ea[(size_t)p2.y * 9 + lane] + ea[(size_t)p3.y * 9 + lane];
        }
    }
    for (; i < ne; i++) {
        int2 p0 = g_se[i];
        float4 a = *(const float4*)&g_u[(size_t)p0.x * 128 + lane * 4];
        acc.x += a.x; acc.y += a.y; acc.z += a.z; acc.w += a.w;
        if (lane < 9) sa += ea[(size_t)p0.y * 9 + lane];
    }
    *(float4*)&g_U1[(size_t)w * 128 + lane * 4] = acc;
    if (lane < 9) g_S[(size_t)w * 9 + lane] = sa;
}

// ---------------- merged weight prep: 0-7 fold_bz, 8-15 fold_bo, 16-25 precomp
__global__ void __launch_bounds__(256) weights_kernel(const float* __restrict__ Wenc,
                                                      const float* __restrict__ W1,
                                                      const float* __restrict__ W2,
                                                      const float* __restrict__ We,
                                                      const float* __restrict__ be) {
    __shared__ float ws[32 * 128];
    const int b = blockIdx.x;
    if (b < 8) {
        const int k0 = b * 16, c = threadIdx.x;
        for (int i = threadIdx.x; i < 512; i += 256)
            ((float4*)ws)[i] = ((const float4*)(Wenc + k0 * 128))[i];
        __syncthreads();
        float acc[16];
#pragma unroll
        for (int r = 0; r < 16; r++) acc[r] = 0.f;
        for (int m = 0; m < 128; m++) {
            float w1 = W1[m * 256 + c];
#pragma unroll
            for (int r = 0; r < 16; r++) acc[r] += ws[r * 128 + m] * w1;
        }
        uint32_t h[8];
#pragma unroll
        for (int r = 0; r < 8; r++) h[r] = pack_f16(acc[2 * r], acc[2 * r + 1]);
        uint4* ph = (uint4*)&g_Bz[c * SAPAD + k0];
        ph[0] = make_uint4(h[0], h[1], h[2], h[3]);
        ph[1] = make_uint4(h[4], h[5], h[6], h[7]);
    } else if (b < 16) {
        const int k0 = (b - 8) * 32;
        const int kc = k0 >> 7, kk0 = k0 & 127;
        for (int i = threadIdx.x; i < 1024; i += 256)
            ((float4*)ws)[i] = ((const float4*)(W2 + k0 * 128))[i];
        __syncthreads();
        const int n = threadIdx.x >> 1, kl0 = (threadIdx.x & 1) * 16;
        uint32_t h[8];
#pragma unroll
        for (int q = 0; q < 8; q++)
            h[q] = pack_f16(ws[(kl0 + 2 * q) * 128 + n], ws[(kl0 + 2 * q + 1) * 128 + n]);
        uint4* ph = (uint4*)&g_Bo[kc * 128 * SAPAD + n * SAPAD + kk0 + kl0];
        ph[0] = make_uint4(h[0], h[1], h[2], h[3]);
        ph[1] = make_uint4(h[4], h[5], h[6], h[7]);
    } else {
        const int j = b - 16, c = threadIdx.x;
        if (c < 128) ws[c] = (j < 9) ? We[j * 128 + c] : be[c];
        __syncthreads();
        float acc = 0.f;
#pragma unroll 8
        for (int m = 0; m < 128; m++) acc += ws[m] * W1[(128 + m) * 256 + c];
        if (j < 9) g_P[j * 256 + c] = acc;
        else       g_q1[c] = acc;
    }
}

// ---------------- kernel 5: HMMA gemm_z (fp16 single-term) -------------------
#define ZA    0
#define ZB    34816
#define ZP    104448
#define ZQ1   113664
#define ZPC   114688
#define ZSS   115712
#define ZCS   121856
#define ZCQ   122880
#define ZSMEM 123904

__global__ void __launch_bounds__(256, 1) gemm_z_tc(const float* __restrict__ b1) {
    extern __shared__ __align__(16) unsigned char sm[];
    const uint32_t sbase = smem_u32(sm);
    const int tid = threadIdx.x, w = tid >> 5, lid = tid & 31;
    const int rowBase = blockIdx.x * 128;
    float* Psm = (float*)(sm + ZP);
    float* Q1s = (float*)(sm + ZQ1);
    float* PCs = (float*)(sm + ZPC);
    float* Ssm = (float*)(sm + ZSS);
    float* CSs = (float*)(sm + ZCS);
    float* CQs = (float*)(sm + ZCQ);

    for (int i = tid; i < 2304; i += 256) Psm[i] = g_P[i];
    Q1s[tid] = g_q1[tid];
    PCs[tid] = g_P[7 * 256 + tid] + b1[tid];
    CSs[tid] = 0.f;
    CQs[tid] = 0.f;
    for (int i = tid; i < 1280; i += 256) {
        int r = i / 10, j = i % 10;
        int grow = rowBase + r;
        float v = 0.f;
        if (grow < NND)
            v = (j < 9) ? g_S[(size_t)grow * 9 + j]
                        : (float)(g_off[grow + 1] - g_off[grow]);
        Ssm[r * 12 + j] = v;
    }
    // stage A (fp16 single plane)
    {
        int r = tid >> 1, ch = (tid & 1) * 64;
        int grow = rowBase + r;
        __half* ah = (__half*)(sm + ZA);
        if (grow < NND) {
            const float* src = &g_U1[(size_t)grow * 128 + ch];
#pragma unroll
            for (int j = 0; j < 16; j++)
                store_h4(ah, r * SAPAD + ch + j * 4, *(const float4*)&src[j * 4]);
        } else {
            float4 zz = make_float4(0.f, 0.f, 0.f, 0.f);
#pragma unroll
            for (int j = 0; j < 16; j++) store_h4(ah, r * SAPAD + ch + j * 4, zz);
        }
    }
    for (int i = tid * 16; i < 69632; i += 256 * 16)
        *(float4*)(sm + ZB + i) = *(const float4*)((const unsigned char*)g_Bz + i);
    __syncthreads();

    float acc[8][4][4];
#pragma unroll
    for (int m = 0; m < 8; m++)
#pragma unroll
        for (int n = 0; n < 4; n++)
#pragma unroll
            for (int e = 0; e < 4; e++) acc[m][n][e] = 0.f;

    const uint32_t a_lane = (uint32_t)((((lid & 7) + 8 * ((lid >> 3) & 1)) * SAPAD + 8 * (lid >> 4)) * 2);
    const uint32_t b_lane = (uint32_t)((((lid & 7) + 8 * (lid >> 4)) * SAPAD + 8 * ((lid >> 3) & 1)) * 2);
    const uint32_t ab = sbase + ZA + a_lane;
    const uint32_t bb = sbase + ZB + b_lane + (uint32_t)(w * 32 * SAPAD) * 2;

#pragma unroll
    for (int kt = 0; kt < 8; kt++) {
        uint32_t k2 = kt * 32;
        uint32_t af[8][4];
#pragma unroll
        for (int mt = 0; mt < 8; mt++)
            ldsm4(af[mt][0], af[mt][1], af[mt][2], af[mt][3],
                  ab + mt * (16 * SAPAD * 2) + k2);
        uint32_t bf0[4], bf1[4];
        ldsm4(bf0[0], bf0[1], bf0[2], bf0[3], bb + k2);
        ldsm4(bf1[0], bf1[1], bf1[2], bf1[3], bb + 16 * SAPAD * 2 + k2);
#pragma unroll
        for (int mt = 0; mt < 8; mt++) {
            mma_f16(acc[mt][0], af[mt], bf0[0], bf0[1]);
            mma_f16(acc[mt][1], af[mt], bf0[2], bf0[3]);
            mma_f16(acc[mt][2], af[mt], bf1[0], bf1[1]);
            mma_f16(acc[mt][3], af[mt], bf1[2], bf1[3]);
        }
    }

    // epilogue
    const int gid = lid >> 2, tig = lid & 3;
    float colS[8], colQ[8];
#pragma unroll
    for (int e = 0; e < 8; e++) { colS[e] = 0.f; colQ[e] = 0.f; }
#pragma unroll
    for (int mt = 0; mt < 8; mt++) {
        int r0 = mt * 16 + gid, r1 = r0 + 8;
        int gr0 = rowBase + r0, gr1 = rowBase + r1;
        bool v0 = gr0 < NND, v1 = gr1 < NND;
        float s0[10], s1[10];
#pragma unroll
        for (int j = 0; j < 10; j++) { s0[j] = Ssm[r0 * 12 + j]; s1[j] = Ssm[r1 * 12 + j]; }
        float d0 = s0[9] + 1.f, d1v = s1[9] + 1.f;
#pragma unroll
        for (int nt = 0; nt < 4; nt++) {
            int c0 = w * 32 + nt * 8 + 2 * tig, c1 = c0 + 1;
            float v00 = acc[mt][nt][0] + d0 * Q1s[c0] + PCs[c0];
            float v01 = acc[mt][nt][1] + d0 * Q1s[c1] + PCs[c1];
            float v10 = acc[mt][nt][2] + d1v * Q1s[c0] + PCs[c0];
            float v11 = acc[mt][nt][3] + d1v * Q1s[c1] + PCs[c1];
#pragma unroll
            for (int j = 0; j < 9; j++) {
                float p0 = Psm[j * 256 + c0], p1 = Psm[j * 256 + c1];
                v00 += s0[j] * p0; v01 += s0[j] * p1;
                v10 += s1[j] * p0; v11 += s1[j] * p1;
            }
            if (v0) {
                *(float2*)&g_z[(size_t)gr0 * 256 + c0] = make_float2(v00, v01);
                colS[nt * 2] += v00; colQ[nt * 2] += v00 * v00;
                colS[nt * 2 + 1] += v01; colQ[nt * 2 + 1] += v01 * v01;
            }
            if (v1) {
                *(float2*)&g_z[(size_t)gr1 * 256 + c0] = make_float2(v10, v11);
                colS[nt * 2] += v10; colQ[nt * 2] += v10 * v10;
                colS[nt * 2 + 1] += v11; colQ[nt * 2 + 1] += v11 * v11;
            }
        }
    }
#pragma unroll
    for (int nt = 0; nt < 4; nt++) {
#pragma unroll
        for (int e = 0; e < 2; e++) {
            int c = w * 32 + nt * 8 + 2 * tig + e;
            atomicAdd(&CSs[c], colS[nt * 2 + e]);
            atomicAdd(&CQs[c], colQ[nt * 2 + e]);
        }
    }
    __syncthreads();
    atomicAdd(&g_cs[tid], CSs[tid]);
    atomicAdd(&g_cq[tid], CQs[tid]);
}

// ---------------- kernel 6: BN finalize --------------------------------------
__global__ void bn_kernel(const float* __restrict__ gamma,
                          const float* __restrict__ beta) {
    int c = threadIdx.x;
    const float invN = 1.f / (float)NND;
    float m = g_cs[c] * invN;
    float var = g_cq[c] * invN - m * m;
    float av = gamma[c] * rsqrtf(var + 1e-5f);
    g_a[c] = av;
    g_bb[c] = beta[c] - m * av;
}

// ---------------- kernel 7: HMMA gemm_o (fp16 single-term) -------------------
#define OA    0
#define OB    34816
#define OSA   104448
#define OSB   105472
#define OB2   106496
#define OSMEM 107008

__global__ void __launch_bounds__(256, 1) gemm_o_tc(const float* __restrict__ b2,
                                                    float* __restrict__ out) {
    extern __shared__ __align__(16) unsigned char sm[];
    const uint32_t sbase = smem_u32(sm);
    const int tid = threadIdx.x, w = tid >> 5, lid = tid & 31;
    const int rowBase = blockIdx.x * 128;
    float* SAs = (float*)(sm + OSA);
    float* SBs = (float*)(sm + OSB);
    float* B2s = (float*)(sm + OB2);
    SAs[tid] = g_a[tid];
    SBs[tid] = g_bb[tid];
    if (tid < 128) B2s[tid] = b2[tid];
    for (int i = tid * 16; i < 69632; i += 256 * 16)
        *(float4*)(sm + OB + i) = *(const float4*)((const unsigned char*)g_Bo + i);

    float acc[4][4][4];
#pragma unroll
    for (int m = 0; m < 4; m++)
#pragma unroll
        for (int n = 0; n < 4; n++)
#pragma unroll
            for (int e = 0; e < 4; e++) acc[m][n][e] = 0.f;

    const uint32_t a_lane = (uint32_t)((((lid & 7) + 8 * ((lid >> 3) & 1)) * SAPAD + 8 * (lid >> 4)) * 2);
    const uint32_t b_lane = (uint32_t)((((lid & 7) + 8 * (lid >> 4)) * SAPAD + 8 * ((lid >> 3) & 1)) * 2);
    const uint32_t a_mbase = (uint32_t)((w >> 2) * 64 * SAPAD * 2);
    const uint32_t b_nbase = (uint32_t)((w & 3) * 32 * SAPAD * 2);

    for (int kc = 0; kc < 2; kc++) {
        __syncthreads();
        {
            int r = tid >> 1, ch = (tid & 1) * 64;
            int grow = rowBase + r;
            __half* ah = (__half*)(sm + OA);
            if (grow < NND) {
                const float* src = &g_z[(size_t)grow * 256 + kc * 128 + ch];
#pragma unroll
                for (int j = 0; j < 16; j++) {
                    float4 g = *(const float4*)&src[j * 4];
                    int c0 = kc * 128 + ch + j * 4;
                    g.x = fmaxf(g.x * SAs[c0 + 0] + SBs[c0 + 0], 0.f);
                    g.y = fmaxf(g.y * SAs[c0 + 1] + SBs[c0 + 1], 0.f);
                    g.z = fmaxf(g.z * SAs[c0 + 2] + SBs[c0 + 2], 0.f);
                    g.w = fmaxf(g.w * SAs[c0 + 3] + SBs[c0 + 3], 0.f);
                    store_h4(ah, r * SAPAD + ch + j * 4, g);
                }
            } else {
                float4 zz = make_float4(0.f, 0.f, 0.f, 0.f);
#pragma unroll
                for (int j = 0; j < 16; j++) store_h4(ah, r * SAPAD + ch + j * 4, zz);
            }
        }
        __syncthreads();
        const uint32_t ab = sbase + OA + a_lane + a_mbase;
        const uint32_t bb = sbase + OB + (uint32_t)(kc * 34816) + b_lane + b_nbase;
#pragma unroll
        for (int kt = 0; kt < 8; kt++) {
            uint32_t k2 = kt * 32;
            uint32_t af[4][4];
#pragma unroll
            for (int mt = 0; mt < 4; mt++)
                ldsm4(af[mt][0], af[mt][1], af[mt][2], af[mt][3],
                      ab + mt * (16 * SAPAD * 2) + k2);
            uint32_t bf0[4], bf1[4];
            ldsm4(bf0[0], bf0[1], bf0[2], bf0[3], bb + k2);
            ldsm4(bf1[0], bf1[1], bf1[2], bf1[3], bb + 16 * SAPAD * 2 + k2);
#pragma unroll
            for (int mt = 0; mt < 4; mt++) {
                mma_f16(acc[mt][0], af[mt], bf0[0], bf0[1]);
                mma_f16(acc[mt][1], af[mt], bf0[2], bf0[3]);
                mma_f16(acc[mt][2], af[mt], bf1[0], bf1[1]);
                mma_f16(acc[mt][3], af[mt], bf1[2], bf1[3]);
            }
        }
    }

    const int gid = lid >> 2, tig = lid & 3;
#pragma unroll
    for (int mt = 0; mt < 4; mt++) {
        int r0 = (w >> 2) * 64 + mt * 16 + gid, r1 = r0 + 8;
        int gr0 = rowBase + r0, gr1 = rowBase + r1;
#pragma unroll
        for (int nt = 0; nt < 4; nt++) {
            int c0 = (w & 3) * 32 + nt * 8 + 2 * tig;
            if (gr0 < NND)
                *(float2*)&out[(size_t)gr0 * 128 + c0] =
                    make_float2(acc[mt][nt][0] + B2s[c0], acc[mt][nt][1] + B2s[c0 + 1]);
            if (gr1 < NND)
                *(float2*)&out[(size_t)gr1 * 128 + c0] =
                    make_float2(acc[mt][nt][2] + B2s[c0], acc[mt][nt][3] + B2s[c0 + 1]);
        }
    }
}

// ---------------- launch ----------------------------------------------------
extern "C" void kernel_launch(void* const* d_in, const int* in_sizes, int n_in,
                              void* d_out, int out_size) {
    const float* x     = (const float*)d_in[0];
    const int*   ei    = (const int*)d_in[1];
    const float* ea    = (const float*)d_in[2];
    const int*   mask  = (const int*)d_in[3];
    const float* pa    = (const float*)d_in[4];
    const float* Wenc  = (const float*)d_in[5];
    const float* We    = (const float*)d_in[6];
    const float* be    = (const float*)d_in[7];
    const float* W1    = (const float*)d_in[8];
    const float* b1    = (const float*)d_in[9];
    const float* gamma = (const float*)d_in[10];
    const float* beta  = (const float*)d_in[11];
    const float* W2    = (const float*)d_in[12];
    const float* b2    = (const float*)d_in[13];
    float*       out   = (float*)d_out;
    const int nmask = in_sizes[3];

    cudaFuncSetAttribute(gemm_z_tc, cudaFuncAttributeMaxDynamicSharedMemorySize, ZSMEM);
    cudaFuncSetAttribute(gemm_o_tc, cudaFuncAttributeMaxDynamicSharedMemorySize, OSMEM);

    void *pcnt, *pcs, *pcq;
    cudaGetSymbolAddress(&pcnt, g_cnt);
    cudaGetSymbolAddress(&pcs, g_cs);
    cudaGetSymbolAddress(&pcq, g_cq);
    cudaMemsetAsync(pcnt, 0, sizeof(int) * NND, 0);
    cudaMemsetAsync(pcs, 0, sizeof(float) * 256, 0);
    cudaMemsetAsync(pcq, 0, sizeof(float) * 256, 0);

    prep_kernel<<<(NND * 32 + 255) / 256, 256>>>(x, pa);
    if (nmask > 0) mask_kernel<<<nmask, 32>>>(mask, nmask);
    hist_kernel<<<(EDG + 255) / 256, 256>>>(ei);
    scan1_kernel<<<NSCB, 256>>>();
    scan2_kernel<<<1, 256>>>();
    scan3_kernel<<<NSCB, 256>>>();
    fill_kernel<<<(EDG + 255) / 256, 256>>>(ei);
    aggregate_kernel<<<(NND * 32 + 255) / 256, 256>>>(ea);
    weights_kernel<<<26, 256>>>(Wenc, W1, W2, We, be);
    gemm_z_tc<<<NTILES, 256, ZSMEM>>>(b1);
    bn_kernel<<<1, 256>>>(gamma, beta);
    gemm_o_tc<<<NTILES, 256, OSMEM>>>(b2, out);
}

// round 16
// speedup vs baseline: 1.1513x; 1.0268x over previous
#include <cuda_runtime.h>
#include <cuda_fp16.h>
#include <cstdint>

#define NND 50000
#define EDG 800000
#define NTILES 391
#define SAPAD 136          // padded k-stride in fp16 (272B = 17x16B, 4-bank shift/row)
#define NSCB 196           // ceil(50000/256) scan blocks
#define PREPB 6250         // prep blocks
#define HISTB 3125         // hist blocks

// ---------------- scratch ----------------------------------------------------
__device__ float g_u[NND * 128];               // masked PReLU(x)
__device__ float g_U1[NND * 128];              // u + sum of u[src] over in-edges
__device__ float g_S[NND * 9];                 // sum of edge_attr over in-edges
__device__ float g_z[NND * 256];               // pre-BN hidden
__device__ float g_P[9 * 256];                 // W_e @ W1_bot
__device__ float g_q1[256];                    // b_e @ W1_bot
__device__ float g_cs[256];                    // column sums of z
__device__ float g_cq[256];                    // column sums of z^2
__device__ __align__(16) __half g_Bz[256 * SAPAD];       // Wfold^T fp16 plane
__device__ __align__(16) __half g_Bo[2 * 128 * SAPAD];   // W2^T [kc] fp16 planes
// CSR scratch
__device__ int g_cnt[NND];
__device__ int g_offp[NND];
__device__ int g_bs[NSCB];
__device__ int g_off[NND + 1];
__device__ int g_cur[NND];
__device__ int2 g_se[EDG];                     // (src, edge_id)

// ---------------- helpers -----------------------------------------------------
__device__ __forceinline__ uint32_t smem_u32(const void* p) {
    uint32_t a;
    asm("{ .reg .u64 t; cvta.to.shared.u64 t, %1; cvt.u32.u64 %0, t; }" : "=r"(a) : "l"(p));
    return a;
}
__device__ __forceinline__ void ldsm4(uint32_t& r0, uint32_t& r1, uint32_t& r2, uint32_t& r3,
                                      uint32_t addr) {
    asm volatile("ldmatrix.sync.aligned.m8n8.x4.shared.b16 {%0,%1,%2,%3}, [%4];"
                 : "=r"(r0), "=r"(r1), "=r"(r2), "=r"(r3) : "r"(addr));
}
__device__ __forceinline__ void mma_f16(float* c, const uint32_t* a, uint32_t b0, uint32_t b1) {
    asm volatile(
        "mma.sync.aligned.m16n8k16.row.col.f32.f16.f16.f32 "
        "{%0,%1,%2,%3}, {%4,%5,%6,%7}, {%8,%9}, {%0,%1,%2,%3};"
        : "+f"(c[0]), "+f"(c[1]), "+f"(c[2]), "+f"(c[3])
        : "r"(a[0]), "r"(a[1]), "r"(a[2]), "r"(a[3]), "r"(b0), "r"(b1));
}
__device__ __forceinline__ uint32_t pack_f16(float a, float b) {
    __half2 h = make_half2(__float2half_rn(a), __float2half_rn(b));
    return *(uint32_t*)&h;
}
__device__ __forceinline__ void store_h4(__half* hi, int idx, float4 g) {
    uint2 h;
    h.x = pack_f16(g.x, g.y);
    h.y = pack_f16(g.z, g.w);
    *(uint2*)&hi[idx] = h;
}

// ---------------- megaA: prep | hist | weights -------------------------------
__global__ void __launch_bounds__(256) megaA_kernel(const float* __restrict__ x,
                                                    const float* __restrict__ pa,
                                                    const int* __restrict__ ei,
                                                    const float* __restrict__ Wenc,
                                                    const float* __restrict__ W1,
                                                    const float* __restrict__ W2,
                                                    const float* __restrict__ We,
                                                    const float* __restrict__ be) {
    __shared__ float ws[32 * 128];
    const int blk = blockIdx.x;
    if (blk < PREPB) {
        // prep: u = PReLU(x)
        const float a = *pa;
        size_t i = (size_t)blk * 256 + threadIdx.x;
        if (i >= (size_t)NND * 32) return;
        float4 g = *(const float4*)&x[i * 4];
        g.x = g.x >= 0.f ? g.x : a * g.x;
        g.y = g.y >= 0.f ? g.y : a * g.y;
        g.z = g.z >= 0.f ? g.z : a * g.z;
        g.w = g.w >= 0.f ? g.w : a * g.w;
        *(float4*)&g_u[i * 4] = g;
    } else if (blk < PREPB + HISTB) {
        // hist
        int e = (blk - PREPB) * 256 + threadIdx.x;
        if (e >= EDG) return;
        unsigned s = (unsigned)ei[e];
        unsigned d = (unsigned)ei[EDG + e];
        if (s >= NND || d >= NND) return;
        atomicAdd(&g_cnt[d], 1);
    } else {
        const int b = blk - PREPB - HISTB;
        if (b < 8) {
            const int k0 = b * 16, c = threadIdx.x;
            for (int i = threadIdx.x; i < 512; i += 256)
                ((float4*)ws)[i] = ((const float4*)(Wenc + k0 * 128))[i];
            __syncthreads();
            float acc[16];
#pragma unroll
            for (int r = 0; r < 16; r++) acc[r] = 0.f;
            for (int m = 0; m < 128; m++) {
                float w1 = W1[m * 256 + c];
#pragma unroll
                for (int r = 0; r < 16; r++) acc[r] += ws[r * 128 + m] * w1;
            }
            uint32_t h[8];
#pragma unroll
            for (int r = 0; r < 8; r++) h[r] = pack_f16(acc[2 * r], acc[2 * r + 1]);
            uint4* ph = (uint4*)&g_Bz[c * SAPAD + k0];
            ph[0] = make_uint4(h[0], h[1], h[2], h[3]);
            ph[1] = make_uint4(h[4], h[5], h[6], h[7]);
        } else if (b < 16) {
            const int k0 = (b - 8) * 32;
            const int kc = k0 >> 7, kk0 = k0 & 127;
            for (int i = threadIdx.x; i < 1024; i += 256)
                ((float4*)ws)[i] = ((const float4*)(W2 + k0 * 128))[i];
            __syncthreads();
            const int n = threadIdx.x >> 1, kl0 = (threadIdx.x & 1) * 16;
            uint32_t h[8];
#pragma unroll
            for (int q = 0; q < 8; q++)
                h[q] = pack_f16(ws[(kl0 + 2 * q) * 128 + n], ws[(kl0 + 2 * q + 1) * 128 + n]);
            uint4* ph = (uint4*)&g_Bo[kc * 128 * SAPAD + n * SAPAD + kk0 + kl0];
            ph[0] = make_uint4(h[0], h[1], h[2], h[3]);
            ph[1] = make_uint4(h[4], h[5], h[6], h[7]);
        } else {
            const int j = b - 16, c = threadIdx.x;
            if (c < 128) ws[c] = (j < 9) ? We[j * 128 + c] : be[c];
            __syncthreads();
            float acc = 0.f;
#pragma unroll 8
            for (int m = 0; m < 128; m++) acc += ws[m] * W1[(128 + m) * 256 + c];
            if (j < 9) g_P[j * 256 + c] = acc;
            else       g_q1[c] = acc;
        }
    }
}

// ---------------- megaB: mask | scan1 ----------------------------------------
__global__ void __launch_bounds__(256) megaB_kernel(const int* __restrict__ idx, int nmask) {
    __shared__ int s[256];
    const int blk = blockIdx.x;
    if (blk < nmask) {
        if (threadIdx.x < 32) {
            unsigned v = (unsigned)idx[blk];
            if (v < NND)
                *(float4*)&g_u[(size_t)v * 128 + threadIdx.x * 4] =
                    make_float4(0.f, 0.f, 0.f, 0.f);
        }
        return;
    }
    const int sb = blk - nmask;   // scan block 0..195
    int t = threadIdx.x;
    int i = sb * 256 + t;
    int v = (i < NND) ? g_cnt[i] : 0;
    int val = v;
    s[t] = val;
    __syncthreads();
#pragma unroll
    for (int off = 1; off < 256; off <<= 1) {
        int add = (t >= off) ? s[t - off] : 0;
        __syncthreads();
        val += add;
        s[t] = val;
        __syncthreads();
    }
    if (i < NND) g_offp[i] = val - v;
    if (t == 255) g_bs[sb] = val;
}

// ---------------- scan23: per-block re-scan of bs + offset write -------------
__global__ void __launch_bounds__(256) scan23_kernel() {
    __shared__ int s[256];
    const int t = threadIdx.x;
    int v = (t < NSCB) ? g_bs[t] : 0;
    int val = v;
    s[t] = val;
    __syncthreads();
#pragma unroll
    for (int off = 1; off < 256; off <<= 1) {
        int add = (t >= off) ? s[t - off] : 0;
        __syncthreads();
        val += add;
        s[t] = val;
        __syncthreads();
    }
    // s[k] = inclusive prefix of bs; exclusive base for block b = s[b]-bs[b]
    __shared__ int base_s, total_s;
    if (t == blockIdx.x) base_s = val - v;
    if (t == 255) total_s = val;
    __syncthreads();
    int base = base_s;
    int i = blockIdx.x * 256 + t;
    if (i < NND) {
        int o = g_offp[i] + base;
        g_off[i] = o;
        g_cur[i] = o;
    }
    if (blockIdx.x == 0 && t == 0) g_off[NND] = total_s;
}

// ---------------- fill --------------------------------------------------------
__global__ void __launch_bounds__(256) fill_kernel(const int* __restrict__ ei) {
    int e = blockIdx.x * 256 + threadIdx.x;
    if (e >= EDG) return;
    unsigned s = (unsigned)ei[e];
    unsigned d = (unsigned)ei[EDG + e];
    if (s >= NND || d >= NND) return;
    int p = atomicAdd(&g_cur[d], 1);
    g_se[p] = make_int2((int)s, e);
}

// ---------------- aggregate (MLP=8): U1[v] = u[v] + sum u[src]; S[v] ---------
__global__ void __launch_bounds__(256) aggregate_kernel(const float* __restrict__ ea) {
    int w = (int)((blockIdx.x * 256u + threadIdx.x) >> 5);
    int lane = threadIdx.x & 31;
    if (w >= NND) return;
    int nb = g_off[w], ne = g_off[w + 1];
    float4 acc = *(const float4*)&g_u[(size_t)w * 128 + lane * 4];
    float sa = 0.f;
    int i = nb;
    for (; i + 8 <= ne; i += 8) {
        int2 p[8];
#pragma unroll
        for (int q = 0; q < 8; q++) p[q] = g_se[i + q];
        float4 r[8];
#pragma unroll
        for (int q = 0; q < 8; q++)
            r[q] = *(const float4*)&g_u[(size_t)p[q].x * 128 + lane * 4];
#pragma unroll
        for (int q = 0; q < 8; q++) {
            acc.x += r[q].x; acc.y += r[q].y; acc.z += r[q].z; acc.w += r[q].w;
        }
        if (lane < 9) {
#pragma unroll
            for (int q = 0; q < 8; q++) sa += ea[(size_t)p[q].y * 9 + lane];
        }
    }
    for (; i < ne; i++) {
        int2 p0 = g_se[i];
        float4 a = *(const float4*)&g_u[(size_t)p0.x * 128 + lane * 4];
        acc.x += a.x; acc.y += a.y; acc.z += a.z; acc.w += a.w;
        if (lane < 9) sa += ea[(size_t)p0.y * 9 + lane];
    }
    *(float4*)&g_U1[(size_t)w * 128 + lane * 4] = acc;
    if (lane < 9) g_S[(size_t)w * 9 + lane] = sa;
}

// ---------------- kernel 5: HMMA gemm_z (fp16 single-term) -------------------
#define ZA    0
#define ZB    34816
#define ZP    104448
#define ZQ1   113664
#define ZPC   114688
#define ZSS   115712
#define ZCS   121856
#define ZCQ   122880
#define ZSMEM 123904

__global__ void __launch_bounds__(256, 1) gemm_z_tc(const float* __restrict__ b1) {
    extern __shared__ __align__(16) unsigned char sm[];
    const uint32_t sbase = smem_u32(sm);
    const int tid = threadIdx.x, w = tid >> 5, lid = tid & 31;
    const int rowBase = blockIdx.x * 128;
    float* Psm = (float*)(sm + ZP);
    float* Q1s = (float*)(sm + ZQ1);
    float* PCs = (float*)(sm + ZPC);
    float* Ssm = (float*)(sm + ZSS);
    float* CSs = (float*)(sm + ZCS);
    float* CQs = (float*)(sm + ZCQ);

    for (int i = tid; i < 2304; i += 256) Psm[i] = g_P[i];
    Q1s[tid] = g_q1[tid];
    PCs[tid] = g_P[7 * 256 + tid] + b1[tid];
    CSs[tid] = 0.f;
    CQs[tid] = 0.f;
    for (int i = tid; i < 1280; i += 256) {
        int r = i / 10, j = i % 10;
        int grow = rowBase + r;
        float v = 0.f;
        if (grow < NND)
            v = (j < 9) ? g_S[(size_t)grow * 9 + j]
                        : (float)(g_off[grow + 1] - g_off[grow]);
        Ssm[r * 12 + j] = v;
    }
    // stage A (fp16 single plane)
    {
        int r = tid >> 1, ch = (tid & 1) * 64;
        int grow = rowBase + r;
        __half* ah = (__half*)(sm + ZA);
        if (grow < NND) {
            const float* src = &g_U1[(size_t)grow * 128 + ch];
#pragma unroll
            for (int j = 0; j < 16; j++)
                store_h4(ah, r * SAPAD + ch + j * 4, *(const float4*)&src[j * 4]);
        } else {
            float4 zz = make_float4(0.f, 0.f, 0.f, 0.f);
#pragma unroll
            for (int j = 0; j < 16; j++) store_h4(ah, r * SAPAD + ch + j * 4, zz);
        }
    }
    for (int i = tid * 16; i < 69632; i += 256 * 16)
        *(float4*)(sm + ZB + i) = *(const float4*)((const unsigned char*)g_Bz + i);
    __syncthreads();

    float acc[8][4][4];
#pragma unroll
    for (int m = 0; m < 8; m++)
#pragma unroll
        for (int n = 0; n < 4; n++)
#pragma unroll
            for (int e = 0; e < 4; e++) acc[m][n][e] = 0.f;

    const uint32_t a_lane = (uint32_t)((((lid & 7) + 8 * ((lid >> 3) & 1)) * SAPAD + 8 * (lid >> 4)) * 2);
    const uint32_t b_lane = (uint32_t)((((lid & 7) + 8 * (lid >> 4)) * SAPAD + 8 * ((lid >> 3) & 1)) * 2);
    const uint32_t ab = sbase + ZA + a_lane;
    const uint32_t bb = sbase + ZB + b_lane + (uint32_t)(w * 32 * SAPAD) * 2;

#pragma unroll
    for (int kt = 0; kt < 8; kt++) {
        uint32_t k2 = kt * 32;
        uint32_t af[8][4];
#pragma unroll
        for (int mt = 0; mt < 8; mt++)
            ldsm4(af[mt][0], af[mt][1], af[mt][2], af[mt][3],
                  ab + mt * (16 * SAPAD * 2) + k2);
        uint32_t bf0[4], bf1[4];
        ldsm4(bf0[0], bf0[1], bf0[2], bf0[3], bb + k2);
        ldsm4(bf1[0], bf1[1], bf1[2], bf1[3], bb + 16 * SAPAD * 2 + k2);
#pragma unroll
        for (int mt = 0; mt < 8; mt++) {
            mma_f16(acc[mt][0], af[mt], bf0[0], bf0[1]);
            mma_f16(acc[mt][1], af[mt], bf0[2], bf0[3]);
            mma_f16(acc[mt][2], af[mt], bf1[0], bf1[1]);
            mma_f16(acc[mt][3], af[mt], bf1[2], bf1[3]);
        }
    }

    // epilogue
    const int gid = lid >> 2, tig = lid & 3;
    float colS[8], colQ[8];
#pragma unroll
    for (int e = 0; e < 8; e++) { colS[e] = 0.f; colQ[e] = 0.f; }
#pragma unroll
    for (int mt = 0; mt < 8; mt++) {
        int r0 = mt * 16 + gid, r1 = r0 + 8;
        int gr0 = rowBase + r0, gr1 = rowBase + r1;
        bool v0 = gr0 < NND, v1 = gr1 < NND;
        float s0[10], s1[10];
#pragma unroll
        for (int j = 0; j < 10; j++) { s0[j] = Ssm[r0 * 12 + j]; s1[j] = Ssm[r1 * 12 + j]; }
        float d0 = s0[9] + 1.f, d1v = s1[9] + 1.f;
#pragma unroll
        for (int nt = 0; nt < 4; nt++) {
            int c0 = w * 32 + nt * 8 + 2 * tig, c1 = c0 + 1;
            float v00 = acc[mt][nt][0] + d0 * Q1s[c0] + PCs[c0];
            float v01 = acc[mt][nt][1] + d0 * Q1s[c1] + PCs[c1];
            float v10 = acc[mt][nt][2] + d1v * Q1s[c0] + PCs[c0];
            float v11 = acc[mt][nt][3] + d1v * Q1s[c1] + PCs[c1];
#pragma unroll
            for (int j = 0; j < 9; j++) {
                float p0 = Psm[j * 256 + c0], p1 = Psm[j * 256 + c1];
                v00 += s0[j] * p0; v01 += s0[j] * p1;
                v10 += s1[j] * p0; v11 += s1[j] * p1;
            }
            if (v0) {
                *(float2*)&g_z[(size_t)gr0 * 256 + c0] = make_float2(v00, v01);
                colS[nt * 2] += v00; colQ[nt * 2] += v00 * v00;
                colS[nt * 2 + 1] += v01; colQ[nt * 2 + 1] += v01 * v01;
            }
            if (v1) {
                *(float2*)&g_z[(size_t)gr1 * 256 + c0] = make_float2(v10, v11);
                colS[nt * 2] += v10; colQ[nt * 2] += v10 * v10;
                colS[nt * 2 + 1] += v11; colQ[nt * 2 + 1] += v11 * v11;
            }
        }
    }
#pragma unroll
    for (int nt = 0; nt < 4; nt++) {
#pragma unroll
        for (int e = 0; e < 2; e++) {
            int c = w * 32 + nt * 8 + 2 * tig + e;
            atomicAdd(&CSs[c], colS[nt * 2 + e]);
            atomicAdd(&CQs[c], colQ[nt * 2 + e]);
        }
    }
    __syncthreads();
    atomicAdd(&g_cs[tid], CSs[tid]);
    atomicAdd(&g_cq[tid], CQs[tid]);
}

// ---------------- kernel 7: HMMA gemm_o (fp16 single-term, fused BN) ---------
#define OA    0
#define OB    34816
#define OSA   104448
#define OSB   105472
#define OB2   106496
#define OSMEM 107008

__global__ void __launch_bounds__(256, 1) gemm_o_tc(const float* __restrict__ gamma,
                                                    const float* __restrict__ beta,
                                                    const float* __restrict__ b2,
                                                    float* __restrict__ out) {
    extern __shared__ __align__(16) unsigned char sm[];
    const uint32_t sbase = smem_u32(sm);
    const int tid = threadIdx.x, w = tid >> 5, lid = tid & 31;
    const int rowBase = blockIdx.x * 128;
    float* SAs = (float*)(sm + OSA);
    float* SBs = (float*)(sm + OSB);
    float* B2s = (float*)(sm + OB2);
    {
        // fused BN finalize (replicated per CTA; trivial cost)
        const float invN = 1.f / (float)NND;
        float m = g_cs[tid] * invN;
        float var = g_cq[tid] * invN - m * m;
        float av = gamma[tid] * rsqrtf(var + 1e-5f);
        SAs[tid] = av;
        SBs[tid] = beta[tid] - m * av;
    }
    if (tid < 128) B2s[tid] = b2[tid];
    for (int i = tid * 16; i < 69632; i += 256 * 16)
        *(float4*)(sm + OB + i) = *(const float4*)((const unsigned char*)g_Bo + i);

    float acc[4][4][4];
#pragma unroll
    for (int m = 0; m < 4; m++)
#pragma unroll
        for (int n = 0; n < 4; n++)
#pragma unroll
            for (int e = 0; e < 4; e++) acc[m][n][e] = 0.f;

    const uint32_t a_lane = (uint32_t)((((lid & 7) + 8 * ((lid >> 3) & 1)) * SAPAD + 8 * (lid >> 4)) * 2);
    const uint32_t b_lane = (uint32_t)((((lid & 7) + 8 * (lid >> 4)) * SAPAD + 8 * ((lid >> 3) & 1)) * 2);
    const uint32_t a_mbase = (uint32_t)((w >> 2) * 64 * SAPAD * 2);
    const uint32_t b_nbase = (uint32_t)((w & 3) * 32 * SAPAD * 2);

    for (int kc = 0; kc < 2; kc++) {
        __syncthreads();
        {
            int r = tid >> 1, ch = (tid & 1) * 64;
            int grow = rowBase + r;
            __half* ah = (__half*)(sm + OA);
            if (grow < NND) {
                const float* src = &g_z[(size_t)grow * 256 + kc * 128 + ch];
#pragma unroll
                for (int j = 0; j < 16; j++) {
                    float4 g = *(const float4*)&src[j * 4];
                    int c0 = kc * 128 + ch + j * 4;
                    g.x = fmaxf(g.x * SAs[c0 + 0] + SBs[c0 + 0], 0.f);
                    g.y = fmaxf(g.y * SAs[c0 + 1] + SBs[c0 + 1], 0.f);
                    g.z = fmaxf(g.z * SAs[c0 + 2] + SBs[c0 + 2], 0.f);
                    g.w = fmaxf(g.w * SAs[c0 + 3] + SBs[c0 + 3], 0.f);
                    store_h4(ah, r * SAPAD + ch + j * 4, g);
                }
            } else {
                float4 zz = make_float4(0.f, 0.f, 0.f, 0.f);
#pragma unroll
                for (int j = 0; j < 16; j++) store_h4(ah, r * SAPAD + ch + j * 4, zz);
            }
        }
        __syncthreads();
        const uint32_t ab = sbase + OA + a_lane + a_mbase;
        const uint32_t bb = sbase + OB + (uint32_t)(kc * 34816) + b_lane + b_nbase;
#pragma unroll
        for (int kt = 0; kt < 8; kt++) {
            uint32_t k2 = kt * 32;
            uint32_t af[4][4];
#pragma unroll
            for (int mt = 0; mt < 4; mt++)
                ldsm4(af[mt][0], af[mt][1], af[mt][2], af[mt][3],
                      ab + mt * (16 * SAPAD * 2) + k2);
            uint32_t bf0[4], bf1[4];
            ldsm4(bf0[0], bf0[1], bf0[2], bf0[3], bb + k2);
            ldsm4(bf1[0], bf1[1], bf1[2], bf1[3], bb + 16 * SAPAD * 2 + k2);
#pragma unroll
            for (int mt = 0; mt < 4; mt++) {
                mma_f16(acc[mt][0], af[mt], bf0[0], bf0[1]);
                mma_f16(acc[mt][1], af[mt], bf0[2], bf0[3]);
                mma_f16(acc[mt][2], af[mt], bf1[0], bf1[1]);
                mma_f16(acc[mt][3], af[mt], bf1[2], bf1[3]);
            }
        }
    }

    const int gid = lid >> 2, tig = lid & 3;
#pragma unroll
    for (int mt = 0; mt < 4; mt++) {
        int r0 = (w >> 2) * 64 + mt * 16 + gid, r1 = r0 + 8;
        int gr0 = rowBase + r0, gr1 = rowBase + r1;
#pragma unroll
        for (int nt = 0; nt < 4; nt++) {
            int c0 = (w & 3) * 32 + nt * 8 + 2 * tig;
            if (gr0 < NND)
                *(float2*)&out[(size_t)gr0 * 128 + c0] =
                    make_float2(acc[mt][nt][0] + B2s[c0], acc[mt][nt][1] + B2s[c0 + 1]);
            if (gr1 < NND)
                *(float2*)&out[(size_t)gr1 * 128 + c0] =
                    make_float2(acc[mt][nt][2] + B2s[c0], acc[mt][nt][3] + B2s[c0 + 1]);
        }
    }
}

// ---------------- launch ----------------------------------------------------
extern "C" void kernel_launch(void* const* d_in, const int* in_sizes, int n_in,
                              void* d_out, int out_size) {
    const float* x     = (const float*)d_in[0];
    const int*   ei    = (const int*)d_in[1];
    const float* ea    = (const float*)d_in[2];
    const int*   mask  = (const int*)d_in[3];
    const float* pa    = (const float*)d_in[4];
    const float* Wenc  = (const float*)d_in[5];
    const float* We    = (const float*)d_in[6];
    const float* be    = (const float*)d_in[7];
    const float* W1    = (const float*)d_in[8];
    const float* b1    = (const float*)d_in[9];
    const float* gamma = (const float*)d_in[10];
    const float* beta  = (const float*)d_in[11];
    const float* W2    = (const float*)d_in[12];
    const float* b2    = (const float*)d_in[13];
    float*       out   = (float*)d_out;
    const int nmask = in_sizes[3];

    cudaFuncSetAttribute(gemm_z_tc, cudaFuncAttributeMaxDynamicSharedMemorySize, ZSMEM);
    cudaFuncSetAttribute(gemm_o_tc, cudaFuncAttributeMaxDynamicSharedMemorySize, OSMEM);

    void *pcnt, *pcs, *pcq;
    cudaGetSymbolAddress(&pcnt, g_cnt);
    cudaGetSymbolAddress(&pcs, g_cs);
    cudaGetSymbolAddress(&pcq, g_cq);
    cudaMemsetAsync(pcnt, 0, sizeof(int) * NND, 0);
    cudaMemsetAsync(pcs, 0, sizeof(float) * 256, 0);
    cudaMemsetAsync(pcq, 0, sizeof(float) * 256, 0);

    megaA_kernel<<<PREPB + HISTB + 26, 256>>>(x, pa, ei, Wenc, W1, W2, We, be);
    megaB_kernel<<<nmask + NSCB, 256>>>(mask, nmask);
    scan23_kernel<<<NSCB, 256>>>();
    fill_kernel<<<(EDG + 255) / 256, 256>>>(ei);
    aggregate_kernel<<<(NND * 32 + 255) / 256, 256>>>(ea);
    gemm_z_tc<<<NTILES, 256, ZSMEM>>>(b1);
    gemm_o_tc<<<NTILES, 256, OSMEM>>>(gamma, beta, b2, out);
}